// round 15
// baseline (speedup 1.0000x reference)
#include <cuda_runtime.h>
#include <cstdint>

#define TT 512
#define IN 64
#define HH 16
#define NC 6
#define NB 1024
#define G4 64
#define CS 8               /* timesteps per chunk */
#define NCHUNK (TT / CS)   /* 64 */
#define CHUNK_BYTES (CS * IN * 4)   /* 2048 */

typedef unsigned long long u64;
typedef unsigned int u32;

__device__ __forceinline__ float fast_tanh(float x) {
    float r; asm("tanh.approx.f32 %0, %1;" : "=f"(r) : "f"(x)); return r;
}
__device__ __forceinline__ float fast_sig(float x) {
    return fmaf(fast_tanh(0.5f * x), 0.5f, 0.5f);
}
__device__ __forceinline__ void ffma2(u64& a, u64 b, u64 c) {
    asm("fma.rn.f32x2 %0, %1, %2, %0;" : "+l"(a) : "l"(b), "l"(c));
}
__device__ __forceinline__ u64 fadd2(u64 a, u64 b) {
    u64 r; asm("add.rn.f32x2 %0, %1, %2;" : "=l"(r) : "l"(a), "l"(b)); return r;
}
__device__ __forceinline__ float2 upk(u64 v) {
    float2 r; asm("mov.b64 {%0, %1}, %2;" : "=f"(r.x), "=f"(r.y) : "l"(v)); return r;
}
__device__ __forceinline__ u64 pk(float x, float y) {
    u64 r; asm("mov.b64 %0, {%1, %2};" : "=l"(r) : "f"(x), "f"(y)); return r;
}
__device__ __forceinline__ void cp_async16(u32 smem_dst, const void* gsrc) {
    asm volatile("cp.async.cg.shared.global [%0], [%1], 16;" :: "r"(smem_dst), "l"(gsrc));
}
__device__ __forceinline__ void cp_commit() {
    asm volatile("cp.async.commit_group;" ::: "memory");
}
__device__ __forceinline__ void cp_wait_all() {
    asm volatile("cp.async.wait_group 0;" ::: "memory");
}

// Block = 1 batch element. Warps 0,1: gate producers (lane owns gate g = tid,
// full w_ih row in regs). Warp 2: recurrence consumer. Double-buffered gate
// chunks + double-buffered cp.async x chunks; one __syncthreads per phase.
// occ 6 (NOT 7): reg cap 113/thread so the producer's 64-reg weight array
// stays register-resident (occ 7's 97-reg cap forced LDL spills -> L1 ~75%).
__global__ __launch_bounds__(96, 6)
void lstm_bsp3_kernel(const float* __restrict__ x,
                      const float* __restrict__ w_ih,
                      const float* __restrict__ w_hh,
                      const float* __restrict__ b_ih,
                      const float* __restrict__ b_hh,
                      const float* __restrict__ w_fc,
                      const float* __restrict__ b_fc,
                      float* __restrict__ out)
{
    const int b    = blockIdx.x;
    const int tid  = threadIdx.x;
    const int w    = tid >> 5;
    const int lane = tid & 31;

    __shared__ __align__(16) float xbuf[2][CS * IN];   // x chunks (cp.async dest)
    __shared__ __align__(16) float gbuf[2][CS][G4];    // gate pre-activations
    __shared__ __align__(16) float s_h[HH];

    if (tid < HH) s_h[tid] = 0.0f;

    const float* xb = x + (size_t)b * TT * IN;

    // ---------------- per-warp persistent state ----------------
    u64 wr[32];            // producers: packed w_ih row of gate g = tid
    float bias = 0.0f;
    u64 hlo[8], hhi[8];    // consumer: packed w_hh rows lane, lane+32
    float cst = 0.0f, afc0 = 0.0f, afc1 = 0.0f, afc2 = 0.0f;
    const float* wf0 = w_fc;

    if (w < 2) {
        const int g = tid;
        const ulonglong2* p = (const ulonglong2*)(w_ih + (size_t)g * IN);
        #pragma unroll
        for (int k = 0; k < 16; k++) { ulonglong2 v = p[k]; wr[2*k] = v.x; wr[2*k+1] = v.y; }
        bias = b_ih[g] + b_hh[g];

        // prologue: async-load chunks 0 and 1 into slots 0 and 1
        u32 s0 = (u32)__cvta_generic_to_shared(&xbuf[0][0]);
        u32 s1 = (u32)__cvta_generic_to_shared(&xbuf[1][0]);
        cp_async16(s0 + tid * 16,        (const char*)xb + tid * 16);
        cp_async16(s0 + 1024 + tid * 16, (const char*)xb + 1024 + tid * 16);
        cp_async16(s1 + tid * 16,        (const char*)xb + CHUNK_BYTES + tid * 16);
        cp_async16(s1 + 1024 + tid * 16, (const char*)xb + CHUNK_BYTES + 1024 + tid * 16);
        cp_commit();
        cp_wait_all();
    } else {
        const int glo = lane, ghi = lane + 32;
        const ulonglong2* p = (const ulonglong2*)(w_hh + (size_t)glo * HH);
        #pragma unroll
        for (int k = 0; k < 4; k++) { ulonglong2 v = p[k]; hlo[2*k] = v.x; hlo[2*k+1] = v.y; }
        p = (const ulonglong2*)(w_hh + (size_t)ghi * HH);
        #pragma unroll
        for (int k = 0; k < 4; k++) { ulonglong2 v = p[k]; hhi[2*k] = v.x; hhi[2*k+1] = v.y; }
        wf0 = w_fc + (size_t)(lane >> 4) * 3 * (TT * HH) + (lane & 15);
    }
    __syncthreads();   // chunks 0,1 visible to all producers

    // prologue: producers compute gbuf[0] <- chunk 0
    if (w < 2) {
        const int g = tid;
        #pragma unroll
        for (int q = 0; q < CS; q++) {
            u64 a0 = pk(bias, 0.f), a1 = 0ull;
            const ulonglong2* xs = (const ulonglong2*)&xbuf[0][q * IN];
            #pragma unroll
            for (int k = 0; k < 16; k++) {
                ulonglong2 xv = xs[k];             // broadcast LDS.128
                ffma2(a0, wr[2*k],   xv.x);
                ffma2(a1, wr[2*k+1], xv.y);
            }
            float2 s2 = upk(fadd2(a0, a1));
            gbuf[0][q][g] = s2.x + s2.y;           // conflict-free STS.32
        }
    }
    __syncthreads();

    float wfa = 0.f, wfb = 0.f, wfc_ = 0.f;
    if (w == 2) { wfa = wf0[0]; wfb = wf0[TT * HH]; wfc_ = wf0[2 * TT * HH]; }

    // ---------------- phases ----------------
    for (int ch = 0; ch < NCHUNK; ch++) {
        if (w < 2) {
            // 1) start async load of chunk ch+2 into slot ch&1 (just freed)
            if (ch + 2 < NCHUNK) {
                u32 sd = (u32)__cvta_generic_to_shared(&xbuf[ch & 1][0]);
                const char* gs = (const char*)xb + (size_t)(ch + 2) * CHUNK_BYTES;
                cp_async16(sd + tid * 16,        gs + tid * 16);
                cp_async16(sd + 1024 + tid * 16, gs + 1024 + tid * 16);
            }
            cp_commit();

            // 2) compute gbuf[(ch+1)&1] <- chunk ch+1 (covers the DRAM latency)
            if (ch + 1 < NCHUNK) {
                const int g = tid;
                const float* xc = &xbuf[(ch + 1) & 1][0];
                float* dst = &gbuf[(ch + 1) & 1][0][0];
                #pragma unroll
                for (int q = 0; q < CS; q++) {
                    u64 a0 = pk(bias, 0.f), a1 = 0ull;
                    const ulonglong2* xs = (const ulonglong2*)(xc + q * IN);
                    #pragma unroll
                    for (int k = 0; k < 16; k++) {
                        ulonglong2 xv = xs[k];     // broadcast LDS.128
                        ffma2(a0, wr[2*k],   xv.x);
                        ffma2(a1, wr[2*k+1], xv.y);
                    }
                    float2 s2 = upk(fadd2(a0, a1));
                    dst[q * G4 + g] = s2.x + s2.y;
                }
            }
            // 3) ensure chunk ch+2 landed before the phase barrier publishes it
            cp_wait_all();
        } else {
            // consume chunk ch from gbuf[ch&1]
            const int glo = lane, ghi = lane + 32;
            const float* src = &gbuf[ch & 1][0][0];
            #pragma unroll
            for (int q = 0; q < CS; q++) {
                const int t = ch * CS + q;
                float gxl = src[q * G4 + glo];
                float gxh = src[q * G4 + ghi];

                float wa = wfa, wb = wfb, wc = wfc_;
                if (t + 1 < TT) {
                    const int to = (t + 1) * HH;
                    wfa  = wf0[to];
                    wfb  = wf0[to + TT * HH];
                    wfc_ = wf0[to + 2 * TT * HH];
                }

                u64 alo0 = pk(gxl, 0.f), alo1 = 0ull;
                u64 ahi0 = pk(gxh, 0.f), ahi1 = 0ull;
                const ulonglong2* hs = (const ulonglong2*)s_h;
                #pragma unroll
                for (int k = 0; k < 4; k++) {
                    ulonglong2 hv = hs[k];          // broadcast LDS.128
                    ffma2(alo0, hlo[2*k],   hv.x);
                    ffma2(alo1, hlo[2*k+1], hv.y);
                    ffma2(ahi0, hhi[2*k],   hv.x);
                    ffma2(ahi1, hhi[2*k+1], hv.y);
                }
                float2 qlo = upk(fadd2(alo0, alo1));
                float2 qhi = upk(fadd2(ahi0, ahi1));
                float v_lo = qlo.x + qlo.y;   // i_j (lane<16) | f_j (lane>=16)
                float v_hi = qhi.x + qhi.y;   // g_j (lane<16) | o_j (lane>=16)

                float fg = __shfl_sync(0xffffffffu, v_lo, (lane + 16) & 31);
                float og = __shfl_sync(0xffffffffu, v_hi, (lane + 16) & 31);

                const bool lo16 = lane < HH;
                float iv = lo16 ? v_lo : fg;
                float fv = lo16 ? fg   : v_lo;
                float gv = lo16 ? v_hi : og;
                float ov = lo16 ? og   : v_hi;

                cst = fast_sig(fv) * cst + fast_sig(iv) * fast_tanh(gv);
                float h = fast_sig(ov) * fast_tanh(cst);

                if (lo16) s_h[lane] = h;   // ordered after shfl (dataflow)
                __syncwarp();              // visible before next step's LDS

                afc0 = fmaf(h, wa, afc0);
                afc1 = fmaf(h, wb, afc1);
                afc2 = fmaf(h, wc, afc2);
            }
        }
        __syncthreads();   // phase barrier: buffers swap roles
    }

    // ---------------- epilogue: FC reduction (consumer warp) ----------------
    if (w == 2) {
        #pragma unroll
        for (int off = 8; off >= 1; off >>= 1) {
            afc0 += __shfl_xor_sync(0xffffffffu, afc0, off);
            afc1 += __shfl_xor_sync(0xffffffffu, afc1, off);
            afc2 += __shfl_xor_sync(0xffffffffu, afc2, off);
        }
        if (lane == 0) {
            out[b * NC + 0] = afc0 + b_fc[0];
            out[b * NC + 1] = afc1 + b_fc[1];
            out[b * NC + 2] = afc2 + b_fc[2];
        } else if (lane == 16) {
            out[b * NC + 3] = afc0 + b_fc[3];
            out[b * NC + 4] = afc1 + b_fc[4];
            out[b * NC + 5] = afc2 + b_fc[5];
        }
    }
}

extern "C" void kernel_launch(void* const* d_in, const int* in_sizes, int n_in,
                              void* d_out, int out_size) {
    const float* x    = (const float*)d_in[0];
    const float* w_ih = (const float*)d_in[1];
    const float* w_hh = (const float*)d_in[2];
    const float* b_ih = (const float*)d_in[3];
    const float* b_hh = (const float*)d_in[4];
    const float* w_fc = (const float*)d_in[5];
    const float* b_fc = (const float*)d_in[6];
    float* out = (float*)d_out;

    lstm_bsp3_kernel<<<NB, 96>>>(x, w_ih, w_hh, b_ih, b_hh, w_fc, b_fc, out);
}

// round 16
// speedup vs baseline: 1.5227x; 1.5227x over previous
#include <cuda_runtime.h>
#include <cstdint>

#define TT 512
#define IN 64
#define HH 16
#define NC 6
#define NB 1024
#define G4 64
#define CS 8               /* timesteps per chunk */
#define NCHUNK (TT / CS)   /* 64 */
#define CHUNK_BYTES (CS * IN * 4)   /* 2048 */

typedef unsigned long long u64;
typedef unsigned int u32;

__device__ __forceinline__ float fast_tanh(float x) {
    float r; asm("tanh.approx.f32 %0, %1;" : "=f"(r) : "f"(x)); return r;
}
__device__ __forceinline__ float fast_sig(float x) {
    return fmaf(fast_tanh(0.5f * x), 0.5f, 0.5f);
}
__device__ __forceinline__ void ffma2(u64& a, u64 b, u64 c) {
    asm("fma.rn.f32x2 %0, %1, %2, %0;" : "+l"(a) : "l"(b), "l"(c));
}
__device__ __forceinline__ u64 fadd2(u64 a, u64 b) {
    u64 r; asm("add.rn.f32x2 %0, %1, %2;" : "=l"(r) : "l"(a), "l"(b)); return r;
}
__device__ __forceinline__ float2 upk(u64 v) {
    float2 r; asm("mov.b64 {%0, %1}, %2;" : "=f"(r.x), "=f"(r.y) : "l"(v)); return r;
}
__device__ __forceinline__ u64 pk(float x, float y) {
    u64 r; asm("mov.b64 %0, {%1, %2};" : "=l"(r) : "f"(x), "f"(y)); return r;
}
__device__ __forceinline__ void cp_async16(u32 smem_dst, const void* gsrc) {
    asm volatile("cp.async.cg.shared.global [%0], [%1], 16;" :: "r"(smem_dst), "l"(gsrc));
}
__device__ __forceinline__ void cp_commit() {
    asm volatile("cp.async.commit_group;" ::: "memory");
}
__device__ __forceinline__ void cp_wait_all() {
    asm volatile("cp.async.wait_group 0;" ::: "memory");
}

// Block = 2 batch elements, 192 threads.
//   Warps 0..3: producers holding ONE shared register copy of w_ih:
//     warp w -> rows 32*(w>>1)+lane, k-half (w&1)*32..+32 (16 u64 regs/lane).
//     Each producer computes partial gate sums for BOTH elements.
//   Warps 4,5: recurrence consumers for element 0 / 1; gate = kh0 + kh1 partials.
// Double-buffered gate partials + cp.async x chunks; one __syncthreads/phase.
// occ 4 -> 85-reg cap (producer ~60 fits); 592 resident blocks >= 512 grid = 1 wave.
__global__ __launch_bounds__(192, 4)
void lstm_splitk_kernel(const float* __restrict__ x,
                        const float* __restrict__ w_ih,
                        const float* __restrict__ w_hh,
                        const float* __restrict__ b_ih,
                        const float* __restrict__ b_hh,
                        const float* __restrict__ w_fc,
                        const float* __restrict__ b_fc,
                        float* __restrict__ out)
{
    const int tid  = threadIdx.x;
    const int w    = tid >> 5;
    const int lane = tid & 31;

    __shared__ __align__(16) float xbuf[2][2][CS * IN];      // [elem][slot]
    __shared__ __align__(16) float gbuf[2][2][2][CS][G4];    // [elem][khalf][slot]
    __shared__ __align__(16) float s_h[2][HH];

    if (tid < 2 * HH) s_h[tid >> 4][tid & 15] = 0.0f;

    // ---------------- per-warp persistent state ----------------
    u64 wr[16];            // producers: half-row of w_ih (32 floats)
    float bias = 0.0f;
    u64 hlo[8], hhi[8];    // consumers
    float cst = 0.0f, afc0 = 0.0f, afc1 = 0.0f, afc2 = 0.0f;
    const float* wf0 = w_fc;
    const float* xb0 = x + (size_t)(2 * blockIdx.x) * TT * IN;
    const float* xb1 = x + (size_t)(2 * blockIdx.x + 1) * TT * IN;

    if (w < 4) {
        const int row = 32 * (w >> 1) + lane;   // gate row 0..63
        const int kh  = w & 1;                  // k-half
        const ulonglong2* p = (const ulonglong2*)(w_ih + (size_t)row * IN + kh * 32);
        #pragma unroll
        for (int k = 0; k < 8; k++) { ulonglong2 v = p[k]; wr[2*k] = v.x; wr[2*k+1] = v.y; }
        bias = (kh == 0) ? (b_ih[row] + b_hh[row]) : 0.0f;

        // prologue cp.async: warps 0,1 stage element 0; warps 2,3 element 1.
        const int ep = w >> 1;
        const int pl = (w & 1) * 32 + lane;     // 0..63 within element
        const float* xbe = ep ? xb1 : xb0;
        u32 s0 = (u32)__cvta_generic_to_shared(&xbuf[ep][0][0]);
        u32 s1 = (u32)__cvta_generic_to_shared(&xbuf[ep][1][0]);
        cp_async16(s0 + pl * 16,        (const char*)xbe + pl * 16);
        cp_async16(s0 + 1024 + pl * 16, (const char*)xbe + 1024 + pl * 16);
        cp_async16(s1 + pl * 16,        (const char*)xbe + CHUNK_BYTES + pl * 16);
        cp_async16(s1 + 1024 + pl * 16, (const char*)xbe + CHUNK_BYTES + 1024 + pl * 16);
        cp_commit();
        cp_wait_all();
    } else {
        const int glo = lane, ghi = lane + 32;
        const ulonglong2* p = (const ulonglong2*)(w_hh + (size_t)glo * HH);
        #pragma unroll
        for (int k = 0; k < 4; k++) { ulonglong2 v = p[k]; hlo[2*k] = v.x; hlo[2*k+1] = v.y; }
        p = (const ulonglong2*)(w_hh + (size_t)ghi * HH);
        #pragma unroll
        for (int k = 0; k < 4; k++) { ulonglong2 v = p[k]; hhi[2*k] = v.x; hhi[2*k+1] = v.y; }
        wf0 = w_fc + (size_t)(lane >> 4) * 3 * (TT * HH) + (lane & 15);
    }
    __syncthreads();   // chunks 0,1 staged for both elements

    // prologue: producers compute gbuf[*][kh][0] <- chunk 0 (both elements)
    if (w < 4) {
        const int row = 32 * (w >> 1) + lane;
        const int kh  = w & 1;
        #pragma unroll
        for (int e = 0; e < 2; e++) {
            const float* xc = &xbuf[e][0][kh * 32];
            float* dst = &gbuf[e][kh][0][0][0];
            #pragma unroll
            for (int q = 0; q < CS; q++) {
                u64 a0 = pk(bias, 0.f), a1 = 0ull;
                const ulonglong2* xs = (const ulonglong2*)(xc + q * IN);
                #pragma unroll
                for (int k = 0; k < 8; k++) {
                    ulonglong2 xv = xs[k];         // broadcast LDS.128
                    ffma2(a0, wr[2*k],   xv.x);
                    ffma2(a1, wr[2*k+1], xv.y);
                }
                float2 s2 = upk(fadd2(a0, a1));
                dst[q * G4 + row] = s2.x + s2.y;   // conflict-free STS.32
            }
        }
    }
    __syncthreads();

    float wfa = 0.f, wfb = 0.f, wfc_ = 0.f;
    if (w >= 4) { wfa = wf0[0]; wfb = wf0[TT * HH]; wfc_ = wf0[2 * TT * HH]; }

    // ---------------- phases ----------------
    for (int ch = 0; ch < NCHUNK; ch++) {
        if (w < 4) {
            const int row = 32 * (w >> 1) + lane;
            const int kh  = w & 1;
            const int ep  = w >> 1;
            const int pl  = (w & 1) * 32 + lane;
            // 1) async load chunk ch+2 into xbuf[ep][ch&1] (just freed)
            if (ch + 2 < NCHUNK) {
                const float* xbe = ep ? xb1 : xb0;
                u32 sd = (u32)__cvta_generic_to_shared(&xbuf[ep][ch & 1][0]);
                const char* gs = (const char*)xbe + (size_t)(ch + 2) * CHUNK_BYTES;
                cp_async16(sd + pl * 16,        gs + pl * 16);
                cp_async16(sd + 1024 + pl * 16, gs + 1024 + pl * 16);
            }
            cp_commit();

            // 2) compute gbuf[*][kh][(ch+1)&1] <- chunk ch+1 (both elements)
            if (ch + 1 < NCHUNK) {
                #pragma unroll
                for (int e = 0; e < 2; e++) {
                    const float* xc = &xbuf[e][(ch + 1) & 1][kh * 32];
                    float* dst = &gbuf[e][kh][(ch + 1) & 1][0][0];
                    #pragma unroll
                    for (int q = 0; q < CS; q++) {
                        u64 a0 = pk(bias, 0.f), a1 = 0ull;
                        const ulonglong2* xs = (const ulonglong2*)(xc + q * IN);
                        #pragma unroll
                        for (int k = 0; k < 8; k++) {
                            ulonglong2 xv = xs[k];
                            ffma2(a0, wr[2*k],   xv.x);
                            ffma2(a1, wr[2*k+1], xv.y);
                        }
                        float2 s2 = upk(fadd2(a0, a1));
                        dst[q * G4 + row] = s2.x + s2.y;
                    }
                }
            }
            cp_wait_all();   // chunk ch+2 landed before the phase barrier
        } else {
            // consumer warp: element e = w-4
            const int e = w - 4;
            const int glo = lane, ghi = lane + 32;
            const float* gA = &gbuf[e][0][ch & 1][0][0];
            const float* gB = &gbuf[e][1][ch & 1][0][0];
            #pragma unroll
            for (int q = 0; q < CS; q++) {
                const int t = ch * CS + q;
                float gxl = gA[q * G4 + glo] + gB[q * G4 + glo];
                float gxh = gA[q * G4 + ghi] + gB[q * G4 + ghi];

                float wa = wfa, wb = wfb, wc = wfc_;
                if (t + 1 < TT) {
                    const int to = (t + 1) * HH;
                    wfa  = wf0[to];
                    wfb  = wf0[to + TT * HH];
                    wfc_ = wf0[to + 2 * TT * HH];
                }

                u64 alo0 = pk(gxl, 0.f), alo1 = 0ull;
                u64 ahi0 = pk(gxh, 0.f), ahi1 = 0ull;
                const ulonglong2* hs = (const ulonglong2*)s_h[e];
                #pragma unroll
                for (int k = 0; k < 4; k++) {
                    ulonglong2 hv = hs[k];          // broadcast LDS.128
                    ffma2(alo0, hlo[2*k],   hv.x);
                    ffma2(alo1, hlo[2*k+1], hv.y);
                    ffma2(ahi0, hhi[2*k],   hv.x);
                    ffma2(ahi1, hhi[2*k+1], hv.y);
                }
                float2 qlo = upk(fadd2(alo0, alo1));
                float2 qhi = upk(fadd2(ahi0, ahi1));
                float v_lo = qlo.x + qlo.y;   // i_j (lane<16) | f_j (lane>=16)
                float v_hi = qhi.x + qhi.y;   // g_j (lane<16) | o_j (lane>=16)

                float fg = __shfl_sync(0xffffffffu, v_lo, (lane + 16) & 31);
                float og = __shfl_sync(0xffffffffu, v_hi, (lane + 16) & 31);

                const bool lo16 = lane < HH;
                float iv = lo16 ? v_lo : fg;
                float fv = lo16 ? fg   : v_lo;
                float gv = lo16 ? v_hi : og;
                float ov = lo16 ? og   : v_hi;

                cst = fast_sig(fv) * cst + fast_sig(iv) * fast_tanh(gv);
                float h = fast_sig(ov) * fast_tanh(cst);

                if (lo16) s_h[e][lane] = h;   // ordered after shfl (dataflow)
                __syncwarp();                 // visible before next step's LDS

                afc0 = fmaf(h, wa, afc0);
                afc1 = fmaf(h, wb, afc1);
                afc2 = fmaf(h, wc, afc2);
            }
        }
        __syncthreads();   // phase barrier: buffers swap roles
    }

    // ---------------- epilogue: FC reduction (consumer warps) ----------------
    if (w >= 4) {
        const int e = w - 4;
        const int b = 2 * blockIdx.x + e;
        #pragma unroll
        for (int off = 8; off >= 1; off >>= 1) {
            afc0 += __shfl_xor_sync(0xffffffffu, afc0, off);
            afc1 += __shfl_xor_sync(0xffffffffu, afc1, off);
            afc2 += __shfl_xor_sync(0xffffffffu, afc2, off);
        }
        if (lane == 0) {
            out[b * NC + 0] = afc0 + b_fc[0];
            out[b * NC + 1] = afc1 + b_fc[1];
            out[b * NC + 2] = afc2 + b_fc[2];
        } else if (lane == 16) {
            out[b * NC + 3] = afc0 + b_fc[3];
            out[b * NC + 4] = afc1 + b_fc[4];
            out[b * NC + 5] = afc2 + b_fc[5];
        }
    }
}

extern "C" void kernel_launch(void* const* d_in, const int* in_sizes, int n_in,
                              void* d_out, int out_size) {
    const float* x    = (const float*)d_in[0];
    const float* w_ih = (const float*)d_in[1];
    const float* w_hh = (const float*)d_in[2];
    const float* b_ih = (const float*)d_in[3];
    const float* b_hh = (const float*)d_in[4];
    const float* w_fc = (const float*)d_in[5];
    const float* b_fc = (const float*)d_in[6];
    float* out = (float*)d_out;

    lstm_splitk_kernel<<<NB / 2, 192>>>(x, w_ih, w_hh, b_ih, b_hh, w_fc, b_fc, out);
}